// round 9
// baseline (speedup 1.0000x reference)
#include <cuda_runtime.h>
#include <cuda_bf16.h>
#include <cstdint>

// Problem constants
#define B_    4
#define H_    16
#define N_    8192
#define DE    64
#define SPLIT 16
#define TM    64
#define EPSV  1e-10f

#define KV_OFF   ((long long)B_ * H_ * N_ * DE)
#define NORM_OFF (KV_OFF + (long long)B_ * H_ * DE * DE)

// XOR-swizzled bf16 tiles: 64 rows x 128 bytes = 8192 B each.
// K is double-buffered (hi+lo per stage). Denominator (past_norm) and the
// GEMM2 norm column live in tiny 16B-row side tiles (P2 / V2).
#define K0HI   0          // K stage 0: hi at +0, lo at +8192
#define K1HI   16384      // K stage 1
#define QHI    32768
#define VHI    40960      // v' hi; lo at +8192
#define PHI    57344      // pkv hi; lo at +8192
#define P2HI   73728      // [64][8] bf16, col0 = norm (hi); lo at +1024
#define V2HI   75776      // [64][8] bf16, col0 = 1.0
#define SMEM_TOTAL 76800  // 3 CTAs/SM (230400 <= 233472)

#define SWX(o) ((o) ^ (((o) >> 3) & 0x70))

union F4 { float4 v; float a[4]; };

// ---------------------------------------------------------------------------
__device__ __forceinline__ uint32_t smem_u32(const void* p) {
    uint32_t a;
    asm("{ .reg .u64 t; cvta.to.shared.u64 t, %1; cvt.u32.u64 %0, t; }"
        : "=r"(a) : "l"(p));
    return a;
}
__device__ __forceinline__ char* swp(char* p, uint32_t x) {
    return (char*)((uintptr_t)p ^ (uintptr_t)x);
}
__device__ __forceinline__ void ldsm4(uint32_t* r, uint32_t addr) {
    asm("ldmatrix.sync.aligned.m8n8.x4.shared.b16 {%0,%1,%2,%3}, [%4];"
        : "=r"(r[0]), "=r"(r[1]), "=r"(r[2]), "=r"(r[3]) : "r"(addr) : "memory");
}
__device__ __forceinline__ void ldsm4t(uint32_t* r, uint32_t addr) {
    asm("ldmatrix.sync.aligned.m8n8.x4.trans.shared.b16 {%0,%1,%2,%3}, [%4];"
        : "=r"(r[0]), "=r"(r[1]), "=r"(r[2]), "=r"(r[3]) : "r"(addr) : "memory");
}
__device__ __forceinline__ void ldsm2t(uint32_t* r, uint32_t addr) {
    asm("ldmatrix.sync.aligned.m8n8.x2.trans.shared.b16 {%0,%1}, [%2];"
        : "=r"(r[0]), "=r"(r[1]) : "r"(addr) : "memory");
}
__device__ __forceinline__ void mma16816(float* c, const uint32_t* a, const uint32_t* b) {
    asm("mma.sync.aligned.m16n8k16.row.col.f32.bf16.bf16.f32 "
        "{%0,%1,%2,%3}, {%4,%5,%6,%7}, {%8,%9}, {%0,%1,%2,%3};"
        : "+f"(c[0]), "+f"(c[1]), "+f"(c[2]), "+f"(c[3])
        : "r"(a[0]), "r"(a[1]), "r"(a[2]), "r"(a[3]), "r"(b[0]), "r"(b[1]));
}
__device__ __forceinline__ void pf_l2(const float* p) {
    asm("prefetch.global.L2 [%0];" :: "l"(p));
}
__device__ __forceinline__ float elu1(float x) {
    return x > 0.f ? x + 1.f : __expf(x);
}
__device__ __forceinline__ unsigned packbf(float x, float y) {
    __nv_bfloat162 t(__float2bfloat16(x), __float2bfloat16(y));
    return *reinterpret_cast<unsigned*>(&t);
}
__device__ __forceinline__ void splitf(float x, float& hi, float& lo) {
    hi = __bfloat162float(__float2bfloat16(x));
    lo = x - hi;
}

// ---------------------------------------------------------------------------
__global__ void fw_init(const float* __restrict__ pkv,
                        const float* __restrict__ pnorm,
                        float* __restrict__ dout) {
    int i = blockIdx.x * blockDim.x + threadIdx.x;
    if (i < B_ * H_ * DE * DE) dout[KV_OFF + i]   = pkv[i];
    if (i < B_ * H_ * DE)      dout[NORM_OFF + i] = pnorm[i];
}

// ---------------------------------------------------------------------------
__global__ __launch_bounds__(256, 3)
void fw_main(const float* __restrict__ keys,
             const float* __restrict__ values,
             const float* __restrict__ queries,
             const float* __restrict__ outin,
             const float* __restrict__ pkv,
             const float* __restrict__ pnorm,
             const float* __restrict__ hg,
             float* __restrict__ dout)
{
    extern __shared__ char smc[];
    const uint32_t sb = smem_u32(smc);

    const int tid  = threadIdx.x;
    const int lane = tid & 31;
    const int w    = tid >> 5;
    const int w03  = w & 3;
    const int wh   = w >> 2;
    const int R0   = w03 * 16;
    const int dR   = w03 * 16;
    const int eoff = wh * 32;
    const int split = blockIdx.x;
    const int bh    = blockIdx.y;
    const int h     = bh & (H_ - 1);

    const float gate  = 1.f / (1.f + __expf(-hg[h]));
    const float gate1 = 1.f - gate;

    // ---- stage pkv (hi/lo, swizzled) + P2 (norm) + V2 (ones column) --------
    {
        const float* pg = pkv + (long long)bh * DE * DE;
        for (int i = tid; i < DE * DE; i += 256) {
            int d = i >> 6, e = i & 63;
            float hi, lo; splitf(pg[i], hi, lo);
            uint32_t off = (uint32_t)d * 128 + e * 2;
            uint32_t x = (uint32_t)(d & 7) << 4;
            *(__nv_bfloat16*)swp(smc + PHI + off, x)        = __float2bfloat16(hi);
            *(__nv_bfloat16*)swp(smc + PHI + 8192 + off, x) = __float2bfloat16(lo);
        }
        const float* pn = pnorm + bh * DE;
        for (int i = tid; i < DE; i += 256) {
            float hi, lo; splitf(pn[i], hi, lo);
            *(uint4*)(smc + P2HI + i * 16)        = make_uint4(packbf(hi, 0.f), 0, 0, 0);
            *(uint4*)(smc + P2HI + 1024 + i * 16) = make_uint4(packbf(lo, 0.f), 0, 0, 0);
            *(uint4*)(smc + V2HI + i * 16)        = make_uint4(packbf(1.f, 0.f), 0, 0, 0);
        }
    }

    // lane-constant swizzle XOR (row&7 == lane&7 for every ldmatrix pattern)
    const uint32_t xa = (uint32_t)(lane & 7) << 4;
    const uint32_t xs = (uint32_t)((tid >> 4) & 7) << 4;   // phase-A stores
    const int g8 = lane >> 2, tig = lane & 3, srcl = (lane >> 2) << 2;
    const uint32_t xv = (uint32_t)(g8 & 7) << 4;           // v' stores

    // per-lane ldmatrix base offsets (row part; col added per call)
    const uint32_t aL   = (uint32_t)(R0 + (lane & 15)) * 128 + ((lane & 16) ? 16 : 0);
    const uint32_t bL   = (uint32_t)(lane & 15) * 128;
    const uint32_t bL4  = bL + ((lane & 16) ? 16 : 0);
    const uint32_t a2L  = (uint32_t)((lane & 7) + ((lane & 16) ? 8 : 0)) * 128
                        + (uint32_t)dR * 2 + ((lane & 8) ? 16 : 0);
    const uint32_t dL   = (uint32_t)(lane & 15) * 16;      // P2/V2 (16B rows)

    float acc2[4][4];
    #pragma unroll
    for (int i = 0; i < 4; i++)
        #pragma unroll
        for (int j = 0; j < 4; j++) acc2[i][j] = 0.f;
    float accn[4] = {0.f, 0.f, 0.f, 0.f};

    const long long baseg = (long long)bh * N_ * DE;
    const int rows_per = N_ / SPLIT;    // 512
    const int row0 = split * rows_per;
    const int ntiles = rows_per / TM;   // 8
    const int c15 = tid & 15;

    for (int t = 0; t < ntiles; t++) {
        const int t0 = t * TM;
        const uint32_t kb = (uint32_t)((t & 1) << 14);     // K0HI or K1HI

        // ---- Phase A: load k,q; elu; bf16 split -> smem (swizzled) ---------
        #pragma unroll
        for (int it = 0; it < 4; it++) {
            int row = (tid >> 4) + it * 16;
            long long g = baseg + (long long)(row0 + t0 + row) * DE + 4 * c15;
            F4 k4, q4;
            k4.v = *(const float4*)(keys + g);
            q4.v = *(const float4*)(queries + g);
            #pragma unroll
            for (int j = 0; j < 4; j++) { k4.a[j] = elu1(k4.a[j]); q4.a[j] = elu1(q4.a[j]); }
            float h0,l0,h1,l1,h2,l2,h3,l3;
            splitf(k4.a[0],h0,l0); splitf(k4.a[1],h1,l1);
            splitf(k4.a[2],h2,l2); splitf(k4.a[3],h3,l3);
            uint32_t off = (uint32_t)row * 128 + 8 * c15;
            *(uint2*)swp(smc + kb + off, xs) =
                make_uint2(packbf(h0,h1), packbf(h2,h3));
            *(uint2*)swp(smc + kb + 8192 + off, xs) =
                make_uint2(packbf(l0,l1), packbf(l2,l3));
            *(uint2*)swp(smc + QHI + off, xs) =
                make_uint2(packbf(q4.a[0],q4.a[1]), packbf(q4.a[2],q4.a[3]));
        }
        __syncthreads();

        // L2 prefetch: next tile (k,q,v) + current tile's outin
        {
            long long gp = baseg + (long long)(row0 + t0 + (tid >> 2)) * DE
                         + (tid & 3) * 16;
            pf_l2(outin + gp);
            if (t + 1 < ntiles) {
                long long gn = gp + (long long)TM * DE;
                pf_l2(keys + gn);
                pf_l2(queries + gn);
                pf_l2(values + gn);
            }
        }

        // ---- GEMM1-k: numer_k (3-term) + denom (P2) ------------------------
        float numk[4][4];
        #pragma unroll
        for (int i = 0; i < 4; i++)
            #pragma unroll
            for (int j = 0; j < 4; j++) numk[i][j] = 0.f;
        float dk[4] = {0.f, 0.f, 0.f, 0.f};

        #pragma unroll
        for (int ks = 0; ks < 4; ks++) {
            uint32_t ah[4], al[4];
            uint32_t ab = (sb + kb + aL + ks * 32) ^ xa;
            ldsm4(ah, ab);
            ldsm4(al, ab + 8192);
            #pragma unroll
            for (int p = 0; p < 2; p++) {
                uint32_t bhf[4], blf[4];
                uint32_t bb = (sb + PHI + (uint32_t)(ks * 16) * 128 + bL4
                               + (uint32_t)wh * 64 + p * 32) ^ xa;
                ldsm4t(bhf, bb);
                ldsm4t(blf, bb + 8192);
                mma16816(numk[2*p],   ah, bhf);
                mma16816(numk[2*p],   ah, blf);
                mma16816(numk[2*p],   al, bhf);
                mma16816(numk[2*p+1], ah, bhf + 2);
                mma16816(numk[2*p+1], ah, blf + 2);
                mma16816(numk[2*p+1], al, bhf + 2);
            }
            uint32_t dh[2], dl[2];
            uint32_t db = sb + P2HI + (uint32_t)(ks * 16) * 16 + dL;
            ldsm2t(dh, db);
            ldsm2t(dl, db + 1024);
            mma16816(dk, ah, dh);
            mma16816(dk, ah, dl);
            mma16816(dk, al, dh);
        }

        // ---- v' = values - numer_k/denom_k -> smem (swizzled) --------------
        {
            float r0v = __frcp_rn(fmaxf(dk[0], EPSV));
            float r2v = __frcp_rn(fmaxf(dk[2], EPSV));
            float rka = __shfl_sync(0xffffffffu, r0v, srcl);
            float rkb = __shfl_sync(0xffffffffu, r2v, srcl);
            const int ra = R0 + g8, rb = ra + 8;
            const long long gra = baseg + (long long)(row0 + t0 + ra) * DE;
            const long long grb = baseg + (long long)(row0 + t0 + rb) * DE;
            #pragma unroll
            for (int nb = 0; nb < 4; nb++) {
                int col = eoff + nb * 8 + tig * 2;
                float2 va = *(const float2*)(values + gra + col);
                float2 vb = *(const float2*)(values + grb + col);
                float n0 = va.x - numk[nb][0] * rka;
                float n1 = va.y - numk[nb][1] * rka;
                float n2 = vb.x - numk[nb][2] * rkb;
                float n3 = vb.y - numk[nb][3] * rkb;
                float h0,l0,h1,l1,h2,l2,h3,l3;
                splitf(n0,h0,l0); splitf(n1,h1,l1);
                splitf(n2,h2,l2); splitf(n3,h3,l3);
                uint32_t oa = (uint32_t)ra * 128 + col * 2;
                uint32_t ob = (uint32_t)rb * 128 + col * 2;
                *(uint32_t*)swp(smc + VHI + oa, xv)        = packbf(h0, h1);
                *(uint32_t*)swp(smc + VHI + 8192 + oa, xv) = packbf(l0, l1);
                *(uint32_t*)swp(smc + VHI + ob, xv)        = packbf(h2, h3);
                *(uint32_t*)swp(smc + VHI + 8192 + ob, xv) = packbf(l2, l3);
            }
        }

        // ---- GEMM1-q: numer_q (1-term; (1-gate)~4.5e-5 masks bf16 error) ---
        float numq[4][4];
        #pragma unroll
        for (int i = 0; i < 4; i++)
            #pragma unroll
            for (int j = 0; j < 4; j++) numq[i][j] = 0.f;
        float dq[4] = {0.f, 0.f, 0.f, 0.f};
        #pragma unroll
        for (int ks = 0; ks < 4; ks++) {
            uint32_t aq[4];
            ldsm4(aq, (sb + QHI + aL + ks * 32) ^ xa);
            #pragma unroll
            for (int p = 0; p < 2; p++) {
                uint32_t bhf[4];
                uint32_t bb = (sb + PHI + (uint32_t)(ks * 16) * 128 + bL4
                               + (uint32_t)wh * 64 + p * 32) ^ xa;
                ldsm4t(bhf, bb);
                mma16816(numq[2*p],   aq, bhf);
                mma16816(numq[2*p+1], aq, bhf + 2);
            }
            uint32_t dh[2];
            ldsm2t(dh, sb + P2HI + (uint32_t)(ks * 16) * 16 + dL);
            mma16816(dq, aq, dh);
        }

        // ---- out_g epilogue ------------------------------------------------
        {
            float r0v = __frcp_rn(fmaxf(dq[0], EPSV));
            float r2v = __frcp_rn(fmaxf(dq[2], EPSV));
            float rqa = __shfl_sync(0xffffffffu, r0v, srcl) * gate1;
            float rqb = __shfl_sync(0xffffffffu, r2v, srcl) * gate1;
            const int ra = R0 + g8, rb = ra + 8;
            const long long gra = baseg + (long long)(row0 + t0 + ra) * DE;
            const long long grb = baseg + (long long)(row0 + t0 + rb) * DE;
            #pragma unroll
            for (int nb = 0; nb < 4; nb++) {
                int col = eoff + nb * 8 + tig * 2;
                float2 oa = *(const float2*)(outin + gra + col);
                float2 ob = *(const float2*)(outin + grb + col);
                float2 ga, gb;
                ga.x = oa.x * gate + numq[nb][0] * rqa;
                ga.y = oa.y * gate + numq[nb][1] * rqa;
                gb.x = ob.x * gate + numq[nb][2] * rqb;
                gb.y = ob.y * gate + numq[nb][3] * rqb;
                *(float2*)(dout + gra + col) = ga;
                *(float2*)(dout + grb + col) = gb;
            }
        }
        __syncthreads();   // v' fully written; K(t) reads still pending below

        // ---- GEMM2: new_kv += k^T v' (3-term); norm via V2 -----------------
        // No trailing barrier: next phase A writes the OTHER K stage and Q
        // (Q reads completed before the barrier above).
        #pragma unroll
        for (int ks = 0; ks < 4; ks++) {
            uint32_t ah[4], al[4];
            uint32_t ab = (sb + kb + a2L + (uint32_t)(ks * 16) * 128) ^ xa;
            ldsm4t(ah, ab);
            ldsm4t(al, ab + 8192);
            #pragma unroll
            for (int p = 0; p < 2; p++) {
                uint32_t bhf[4], blf[4];
                uint32_t bb = (sb + VHI + (uint32_t)(ks * 16) * 128 + bL4
                               + (uint32_t)eoff * 2 + p * 32) ^ xa;
                ldsm4t(bhf, bb);
                ldsm4t(blf, bb + 8192);
                mma16816(acc2[2*p],   ah, bhf);
                mma16816(acc2[2*p],   ah, blf);
                mma16816(acc2[2*p],   al, bhf);
                mma16816(acc2[2*p+1], ah, bhf + 2);
                mma16816(acc2[2*p+1], ah, blf + 2);
                mma16816(acc2[2*p+1], al, bhf + 2);
            }
            if (wh == 1) {   // V2 col0 = 1.0 -> exact sum of k rides the MMA
                uint32_t dh[2];
                ldsm2t(dh, sb + V2HI + (uint32_t)(ks * 16) * 16 + dL);
                mma16816(accn, ah, dh);
                mma16816(accn, al, dh);
            }
        }
    }

    // ---- Epilogue: merge new_kv / new_norm ---------------------------------
    float* kvo = dout + KV_OFF + (long long)bh * DE * DE;
    #pragma unroll
    for (int nb = 0; nb < 4; nb++) {
        int col = eoff + nb * 8 + tig * 2;
        atomicAdd(&kvo[(dR + g8) * DE + col],     acc2[nb][0]);
        atomicAdd(&kvo[(dR + g8) * DE + col + 1], acc2[nb][1]);
        atomicAdd(&kvo[(dR + g8 + 8) * DE + col],     acc2[nb][2]);
        atomicAdd(&kvo[(dR + g8 + 8) * DE + col + 1], acc2[nb][3]);
    }
    if (wh == 1 && tig == 0) {
        float* no = dout + NORM_OFF + (long long)bh * DE;
        atomicAdd(&no[dR + g8],     accn[0]);
        atomicAdd(&no[dR + g8 + 8], accn[2]);
    }
}

// ---------------------------------------------------------------------------
extern "C" void kernel_launch(void* const* d_in, const int* in_sizes, int n_in,
                              void* d_out, int out_size) {
    const float* keys    = (const float*)d_in[0];
    const float* values  = (const float*)d_in[1];
    const float* queries = (const float*)d_in[2];
    const float* outin   = (const float*)d_in[3];
    const float* pkv     = (const float*)d_in[4];
    const float* pnorm   = (const float*)d_in[5];
    const float* hg      = (const float*)d_in[6];
    float* dout = (float*)d_out;

    cudaFuncSetAttribute(fw_main, cudaFuncAttributeMaxDynamicSharedMemorySize,
                         SMEM_TOTAL);

    fw_init<<<(B_ * H_ * DE * DE + 255) / 256, 256>>>(pkv, pnorm, dout);

    dim3 grid(SPLIT, B_ * H_);
    fw_main<<<grid, 256, SMEM_TOTAL>>>(keys, values, queries, outin,
                                       pkv, pnorm, hg, dout);
}

// round 10
// speedup vs baseline: 1.2967x; 1.2967x over previous
#include <cuda_runtime.h>
#include <cuda_bf16.h>
#include <cstdint>

// Problem constants
#define B_    4
#define H_    16
#define N_    8192
#define DE    64
#define SPLIT 16
#define TM    128
#define NT    512
#define EPSV  1e-10f

#define KV_OFF   ((long long)B_ * H_ * N_ * DE)
#define NORM_OFF (KV_OFF + (long long)B_ * H_ * DE * DE)

// bf16 tiles, row stride 72 elements (144 B) — R8-proven conflict-free layout
#define LDBB  144
#define SM_KHI 0                       // [128][72]
#define SM_KLO 18432
#define SM_QHI 36864
#define SM_VHI 55296                   // v' (+ col 64 = 1.0 for norm)
#define SM_VLO 73728
#define SM_PHI 92160                   // pkv hi [64][72] (col 64 = past_norm)
#define SM_PLO 101376
#define SMEM_TOTAL 110592              // -> 2 CTAs/SM, 32 warps/SM

union F4 { float4 v; float a[4]; };

// ---------------------------------------------------------------------------
__device__ __forceinline__ uint32_t smem_u32(const void* p) {
    uint32_t a;
    asm("{ .reg .u64 t; cvta.to.shared.u64 t, %1; cvt.u32.u64 %0, t; }"
        : "=r"(a) : "l"(p));
    return a;
}
__device__ __forceinline__ void ldsm4(uint32_t* r, uint32_t addr) {
    asm("ldmatrix.sync.aligned.m8n8.x4.shared.b16 {%0,%1,%2,%3}, [%4];"
        : "=r"(r[0]), "=r"(r[1]), "=r"(r[2]), "=r"(r[3]) : "r"(addr) : "memory");
}
__device__ __forceinline__ void ldsm4t(uint32_t* r, uint32_t addr) {
    asm("ldmatrix.sync.aligned.m8n8.x4.trans.shared.b16 {%0,%1,%2,%3}, [%4];"
        : "=r"(r[0]), "=r"(r[1]), "=r"(r[2]), "=r"(r[3]) : "r"(addr) : "memory");
}
__device__ __forceinline__ void ldsm2t(uint32_t* r, uint32_t addr) {
    asm("ldmatrix.sync.aligned.m8n8.x2.trans.shared.b16 {%0,%1}, [%2];"
        : "=r"(r[0]), "=r"(r[1]) : "r"(addr) : "memory");
}
__device__ __forceinline__ void mma16816(float* c, const uint32_t* a, const uint32_t* b) {
    asm("mma.sync.aligned.m16n8k16.row.col.f32.bf16.bf16.f32 "
        "{%0,%1,%2,%3}, {%4,%5,%6,%7}, {%8,%9}, {%0,%1,%2,%3};"
        : "+f"(c[0]), "+f"(c[1]), "+f"(c[2]), "+f"(c[3])
        : "r"(a[0]), "r"(a[1]), "r"(a[2]), "r"(a[3]), "r"(b[0]), "r"(b[1]));
}
__device__ __forceinline__ void pf_l2(const float* p) {
    asm("prefetch.global.L2 [%0];" :: "l"(p));
}
__device__ __forceinline__ float elu1(float x) {
    return x > 0.f ? x + 1.f : __expf(x);
}
__device__ __forceinline__ unsigned packbf(float x, float y) {
    __nv_bfloat162 t(__float2bfloat16(x), __float2bfloat16(y));
    return *reinterpret_cast<unsigned*>(&t);
}
__device__ __forceinline__ void splitf(float x, float& hi, float& lo) {
    hi = __bfloat162float(__float2bfloat16(x));
    lo = x - hi;
}

// ---------------------------------------------------------------------------
__global__ void fw_init(const float* __restrict__ pkv,
                        const float* __restrict__ pnorm,
                        float* __restrict__ dout) {
    int i = blockIdx.x * blockDim.x + threadIdx.x;
    if (i < B_ * H_ * DE * DE) dout[KV_OFF + i]   = pkv[i];
    if (i < B_ * H_ * DE)      dout[NORM_OFF + i] = pnorm[i];
}

// ---------------------------------------------------------------------------
__global__ __launch_bounds__(NT, 2)
void fw_main(const float* __restrict__ keys,
             const float* __restrict__ values,
             const float* __restrict__ queries,
             const float* __restrict__ outin,
             const float* __restrict__ pkv,
             const float* __restrict__ pnorm,
             const float* __restrict__ hg,
             float* __restrict__ dout)
{
    extern __shared__ char smc[];
    const uint32_t sb = smem_u32(smc);

    const int tid  = threadIdx.x;
    const int lane = tid & 31;
    const int w    = tid >> 5;          // 0..15
    // GEMM1 / v' / out_g split: 8 row-slices x 2 col-halves
    const int w8   = w & 7;
    const int wh   = w >> 3;
    const int R0   = w8 * 16;
    const int eoff = wh * 32;
    // GEMM2 split: 4 d-slices x 4 e-quarters
    const int dR   = (w & 3) * 16;
    const int eq   = w >> 2;            // 0..3
    const int ecol = eq * 16;

    const int split = blockIdx.x;
    const int bh    = blockIdx.y;
    const int h     = bh & (H_ - 1);

    const float gate  = 1.f / (1.f + __expf(-hg[h]));
    const float gate1 = 1.f - gate;

    // ---- stage pkv (hi/lo) + norm col 64; V const cols 64-71 ---------------
    {
        const float* pg = pkv + (long long)bh * DE * DE;
        for (int i = tid; i < DE * DE; i += NT) {
            int d = i >> 6, e = i & 63;
            float hi, lo; splitf(pg[i], hi, lo);
            *(__nv_bfloat16*)(smc + SM_PHI + d * LDBB + e * 2) = __float2bfloat16(hi);
            *(__nv_bfloat16*)(smc + SM_PLO + d * LDBB + e * 2) = __float2bfloat16(lo);
        }
        const float* pn = pnorm + bh * DE;
        for (int i = tid; i < DE * 8; i += NT) {
            int d = i >> 3, c = 64 + (i & 7);
            float hi = 0.f, lo = 0.f;
            if (c == 64) splitf(pn[d], hi, lo);
            *(__nv_bfloat16*)(smc + SM_PHI + d * LDBB + c * 2) = __float2bfloat16(hi);
            *(__nv_bfloat16*)(smc + SM_PLO + d * LDBB + c * 2) = __float2bfloat16(lo);
        }
        for (int i = tid; i < TM * 8; i += NT) {
            int row = i >> 3, c = 64 + (i & 7);
            *(__nv_bfloat16*)(smc + SM_VHI + row * LDBB + c * 2) =
                __float2bfloat16(c == 64 ? 1.f : 0.f);
            *(__nv_bfloat16*)(smc + SM_VLO + row * LDBB + c * 2) = __float2bfloat16(0.f);
        }
    }

    const uint32_t aoff   = (uint32_t)(lane & 15) * LDBB + ((lane & 16) ? 16 : 0);
    const uint32_t atoff  = (uint32_t)((lane & 7) + ((lane & 16) ? 8 : 0)) * LDBB
                          + ((lane & 8) ? 16 : 0);
    const uint32_t btoff  = (uint32_t)(lane & 15) * LDBB;
    const uint32_t btoff4 = btoff + ((lane & 16) ? 16 : 0);
    const int g8 = lane >> 2, tig = lane & 3, srcl = (lane >> 2) << 2;

    float acc2[2][4];
    #pragma unroll
    for (int i = 0; i < 2; i++)
        #pragma unroll
        for (int j = 0; j < 4; j++) acc2[i][j] = 0.f;
    float accn[4] = {0.f, 0.f, 0.f, 0.f};

    const long long baseg = (long long)bh * N_ * DE;
    const int rows_per = N_ / SPLIT;    // 512
    const int row0 = split * rows_per;
    const int ntiles = rows_per / TM;   // 4
    const int c15 = tid & 15;

    __syncthreads();

    for (int t = 0; t < ntiles; t++) {
        const int t0 = t * TM;

        // ---- Phase A: load k,q; elu; bf16 split -> smem --------------------
        #pragma unroll
        for (int it = 0; it < 4; it++) {
            int row = (tid >> 4) + it * 32;
            long long g = baseg + (long long)(row0 + t0 + row) * DE + 4 * c15;
            F4 k4, q4;
            k4.v = *(const float4*)(keys + g);
            q4.v = *(const float4*)(queries + g);
            #pragma unroll
            for (int j = 0; j < 4; j++) { k4.a[j] = elu1(k4.a[j]); q4.a[j] = elu1(q4.a[j]); }
            float h0,l0,h1,l1,h2,l2,h3,l3;
            splitf(k4.a[0],h0,l0); splitf(k4.a[1],h1,l1);
            splitf(k4.a[2],h2,l2); splitf(k4.a[3],h3,l3);
            uint32_t off = (uint32_t)row * LDBB + 8 * c15;
            *(uint2*)(smc + SM_KHI + off) = make_uint2(packbf(h0,h1), packbf(h2,h3));
            *(uint2*)(smc + SM_KLO + off) = make_uint2(packbf(l0,l1), packbf(l2,l3));
            *(uint2*)(smc + SM_QHI + off) =
                make_uint2(packbf(q4.a[0],q4.a[1]), packbf(q4.a[2],q4.a[3]));
        }
        __syncthreads();

        // L2 prefetch next tile (k,q,v only — no outin, per R9 lesson)
        if (t + 1 < ntiles) {
            long long gp = baseg + (long long)(row0 + t0 + TM + (tid >> 2)) * DE
                         + (tid & 3) * 16;
            pf_l2(keys + gp);
            pf_l2(queries + gp);
            pf_l2(values + gp);
        }

        // ---- GEMM1-k: numer_k (3-term) + denom (col 64) --------------------
        float numk[4][4];
        #pragma unroll
        for (int i = 0; i < 4; i++)
            #pragma unroll
            for (int j = 0; j < 4; j++) numk[i][j] = 0.f;
        float dk[4] = {0.f, 0.f, 0.f, 0.f};

        #pragma unroll
        for (int ks = 0; ks < 4; ks++) {
            uint32_t ah[4], al[4];
            ldsm4(ah, sb + SM_KHI + (uint32_t)R0 * LDBB + ks * 32 + aoff);
            ldsm4(al, sb + SM_KLO + (uint32_t)R0 * LDBB + ks * 32 + aoff);
            #pragma unroll
            for (int p = 0; p < 2; p++) {
                uint32_t bhf[4], blf[4];
                uint32_t bb = sb + SM_PHI + (uint32_t)(ks * 16) * LDBB
                            + (uint32_t)wh * 64 + p * 32 + btoff4;
                ldsm4t(bhf, bb);
                ldsm4t(blf, bb + (SM_PLO - SM_PHI));
                mma16816(numk[2*p],   ah, bhf);
                mma16816(numk[2*p],   ah, blf);
                mma16816(numk[2*p],   al, bhf);
                mma16816(numk[2*p+1], ah, bhf + 2);
                mma16816(numk[2*p+1], ah, blf + 2);
                mma16816(numk[2*p+1], al, bhf + 2);
            }
            uint32_t dh[2], dl[2];
            uint32_t db = sb + SM_PHI + (uint32_t)(ks * 16) * LDBB + 128 + btoff;
            ldsm2t(dh, db);
            ldsm2t(dl, db + (SM_PLO - SM_PHI));
            mma16816(dk, ah, dh);
            mma16816(dk, ah, dl);
            mma16816(dk, al, dh);
        }

        // ---- v' = values - numer_k/denom_k -> smem (bf16 split) ------------
        {
            float r0v = __frcp_rn(fmaxf(dk[0], EPSV));
            float r2v = __frcp_rn(fmaxf(dk[2], EPSV));
            float rka = __shfl_sync(0xffffffffu, r0v, srcl);
            float rkb = __shfl_sync(0xffffffffu, r2v, srcl);
            const int ra = R0 + g8, rb = ra + 8;
            const long long gra = baseg + (long long)(row0 + t0 + ra) * DE;
            const long long grb = baseg + (long long)(row0 + t0 + rb) * DE;
            #pragma unroll
            for (int nb = 0; nb < 4; nb++) {
                int col = eoff + nb * 8 + tig * 2;
                float2 va = *(const float2*)(values + gra + col);
                float2 vb = *(const float2*)(values + grb + col);
                float n0 = va.x - numk[nb][0] * rka;
                float n1 = va.y - numk[nb][1] * rka;
                float n2 = vb.x - numk[nb][2] * rkb;
                float n3 = vb.y - numk[nb][3] * rkb;
                float h0,l0,h1,l1,h2,l2,h3,l3;
                splitf(n0,h0,l0); splitf(n1,h1,l1);
                splitf(n2,h2,l2); splitf(n3,h3,l3);
                uint32_t oa = (uint32_t)ra * LDBB + col * 2;
                uint32_t ob = (uint32_t)rb * LDBB + col * 2;
                *(uint32_t*)(smc + SM_VHI + oa) = packbf(h0, h1);
                *(uint32_t*)(smc + SM_VLO + oa) = packbf(l0, l1);
                *(uint32_t*)(smc + SM_VHI + ob) = packbf(h2, h3);
                *(uint32_t*)(smc + SM_VLO + ob) = packbf(l2, l3);
            }
        }

        // ---- GEMM1-q: numer_q (1-term; (1-gate)~4.5e-5 masks bf16 error) ---
        float numq[4][4];
        #pragma unroll
        for (int i = 0; i < 4; i++)
            #pragma unroll
            for (int j = 0; j < 4; j++) numq[i][j] = 0.f;
        float dq[4] = {0.f, 0.f, 0.f, 0.f};
        #pragma unroll
        for (int ks = 0; ks < 4; ks++) {
            uint32_t aq[4];
            ldsm4(aq, sb + SM_QHI + (uint32_t)R0 * LDBB + ks * 32 + aoff);
            #pragma unroll
            for (int p = 0; p < 2; p++) {
                uint32_t bhf[4];
                ldsm4t(bhf, sb + SM_PHI + (uint32_t)(ks * 16) * LDBB
                            + (uint32_t)wh * 64 + p * 32 + btoff4);
                mma16816(numq[2*p],   aq, bhf);
                mma16816(numq[2*p+1], aq, bhf + 2);
            }
            uint32_t dh[2];
            ldsm2t(dh, sb + SM_PHI + (uint32_t)(ks * 16) * LDBB + 128 + btoff);
            mma16816(dq, aq, dh);
        }

        // ---- out_g epilogue ------------------------------------------------
        {
            float r0v = __frcp_rn(fmaxf(dq[0], EPSV));
            float r2v = __frcp_rn(fmaxf(dq[2], EPSV));
            float rqa = __shfl_sync(0xffffffffu, r0v, srcl) * gate1;
            float rqb = __shfl_sync(0xffffffffu, r2v, srcl) * gate1;
            const int ra = R0 + g8, rb = ra + 8;
            const long long gra = baseg + (long long)(row0 + t0 + ra) * DE;
            const long long grb = baseg + (long long)(row0 + t0 + rb) * DE;
            #pragma unroll
            for (int nb = 0; nb < 4; nb++) {
                int col = eoff + nb * 8 + tig * 2;
                float2 oa = *(const float2*)(outin + gra + col);
                float2 ob = *(const float2*)(outin + grb + col);
                float2 ga, gb;
                ga.x = oa.x * gate + numq[nb][0] * rqa;
                ga.y = oa.y * gate + numq[nb][1] * rqa;
                gb.x = ob.x * gate + numq[nb][2] * rqb;
                gb.y = ob.y * gate + numq[nb][3] * rqb;
                *(float2*)(dout + gra + col) = ga;
                *(float2*)(dout + grb + col) = gb;
            }
        }
        __syncthreads();   // v' fully written

        // ---- GEMM2: new_kv += k^T v' (3-term); norm via col 64 -------------
        #pragma unroll
        for (int ks = 0; ks < 8; ks++) {
            uint32_t ah[4], al[4];
            uint32_t ab = sb + SM_KHI + (uint32_t)(ks * 16) * LDBB + dR * 2 + atoff;
            ldsm4t(ah, ab);
            ldsm4t(al, ab + (SM_KLO - SM_KHI));
            uint32_t bhf[4], blf[4];
            uint32_t bb = sb + SM_VHI + (uint32_t)(ks * 16) * LDBB
                        + (uint32_t)ecol * 2 + btoff4;
            ldsm4t(bhf, bb);
            ldsm4t(blf, bb + (SM_VLO - SM_VHI));
            mma16816(acc2[0], ah, bhf);
            mma16816(acc2[0], ah, blf);
            mma16816(acc2[0], al, bhf);
            mma16816(acc2[1], ah, bhf + 2);
            mma16816(acc2[1], ah, blf + 2);
            mma16816(acc2[1], al, bhf + 2);
            if (eq == 3) {   // v'[.,64]=1 (hi), lo=0 -> exact sum of k
                uint32_t dh[2];
                ldsm2t(dh, sb + SM_VHI + (uint32_t)(ks * 16) * LDBB + 128 + btoff);
                mma16816(accn, ah, dh);
                mma16816(accn, al, dh);
            }
        }
        __syncthreads();   // K/Q/V reads done before next phase A
    }

    // ---- Epilogue: merge new_kv / new_norm ---------------------------------
    float* kvo = dout + KV_OFF + (long long)bh * DE * DE;
    #pragma unroll
    for (int nb = 0; nb < 2; nb++) {
        int col = ecol + nb * 8 + tig * 2;
        atomicAdd(&kvo[(dR + g8) * DE + col],     acc2[nb][0]);
        atomicAdd(&kvo[(dR + g8) * DE + col + 1], acc2[nb][1]);
        atomicAdd(&kvo[(dR + g8 + 8) * DE + col],     acc2[nb][2]);
        atomicAdd(&kvo[(dR + g8 + 8) * DE + col + 1], acc2[nb][3]);
    }
    if (eq == 3 && tig == 0) {
        float* no = dout + NORM_OFF + (long long)bh * DE;
        atomicAdd(&no[dR + g8],     accn[0]);
        atomicAdd(&no[dR + g8 + 8], accn[2]);
    }
}

// ---------------------------------------------------------------------------
extern "C" void kernel_launch(void* const* d_in, const int* in_sizes, int n_in,
                              void* d_out, int out_size) {
    const float* keys    = (const float*)d_in[0];
    const float* values  = (const float*)d_in[1];
    const float* queries = (const float*)d_in[2];
    const float* outin   = (const float*)d_in[3];
    const float* pkv     = (const float*)d_in[4];
    const float* pnorm   = (const float*)d_in[5];
    const float* hg      = (const float*)d_in[6];
    float* dout = (float*)d_out;

    cudaFuncSetAttribute(fw_main, cudaFuncAttributeMaxDynamicSharedMemorySize,
                         SMEM_TOTAL);

    fw_init<<<(B_ * H_ * DE * DE + 255) / 256, 256>>>(pkv, pnorm, dout);

    dim3 grid(SPLIT, B_ * H_);
    fw_main<<<grid, NT, SMEM_TOTAL>>>(keys, values, queries, outin,
                                      pkv, pnorm, hg, dout);
}